// round 15
// baseline (speedup 1.0000x reference)
#include <cuda_runtime.h>
#include <cuda_fp16.h>
#include <math.h>
#include <stdint.h>

#define NN 24000
#define EE 96000
#define BB 1200
#define NPG 20

// ---------------- device scratch ----------------
__device__ __half g_q1h[NN*512];
__device__ __half g_s1h[NN*512];
__device__ __half g_k1h[NN*512];
__device__ __half g_v1h[NN*512];
__device__ __half g_h1h[NN*512];
__device__ float  g_ph1[BB*512];
__device__ __half g_q2h[NN*1024];
__device__ __half g_k2h[NN*1024];
__device__ float  g_z[BB*2048];
__device__ float  g_r[BB*16];
__device__ float  g_cnt[BB];
__device__ int    g_deg[NN];
__device__ int    g_offs[NN+1];
__device__ int    g_cursor[NN];
__device__ int    g_eidx[EE];
__device__ __half g_w2h[2*1024*512];
__device__ __half g_wfinh[1024*1280];
__device__ __half g_cch[BB*1280];
__device__ float  g_fppart[4*BB*256];
__device__ float  g_fpart[4*BB*1024];

// ---------------- side stream + events ----------------
static cudaStream_t g_sB;
static cudaEvent_t  g_evA0, g_evCSR, g_evB1, g_evB2, g_evProj, g_evH1, g_evG0, g_evZ0;
namespace {
struct StreamInit {
    StreamInit() {
        cudaStreamCreateWithFlags(&g_sB, cudaStreamNonBlocking);
        cudaEventCreateWithFlags(&g_evA0,  cudaEventDisableTiming);
        cudaEventCreateWithFlags(&g_evCSR, cudaEventDisableTiming);
        cudaEventCreateWithFlags(&g_evB1,  cudaEventDisableTiming);
        cudaEventCreateWithFlags(&g_evB2,  cudaEventDisableTiming);
        cudaEventCreateWithFlags(&g_evProj,cudaEventDisableTiming);
        cudaEventCreateWithFlags(&g_evH1,  cudaEventDisableTiming);
        cudaEventCreateWithFlags(&g_evG0,  cudaEventDisableTiming);
        cudaEventCreateWithFlags(&g_evZ0,  cudaEventDisableTiming);
    }
};
static StreamInit g_streamInit;
}

__device__ __forceinline__ void cpa16(void* dst, const void* src, bool pred) {
    uint32_t d = (uint32_t)__cvta_generic_to_shared(dst);
    int sz = pred ? 16 : 0;
    asm volatile("cp.async.cg.shared.global [%0], [%1], 16, %2;\n"
                 :: "r"(d), "l"(src), "r"(sz));
}

// ---------------- CSR build ----------------
__global__ void zero_deg_kernel() {
    int i = blockIdx.x*blockDim.x + threadIdx.x;
    if (i < NN) g_deg[i] = 0;
}

__global__ void hist_kernel(const int* __restrict__ dst) {
    int e = blockIdx.x*blockDim.x + threadIdx.x;
    if (e < EE) atomicAdd(&g_deg[dst[e]], 1);
}

__global__ void scan_kernel() {
    __shared__ int wsum[32];
    __shared__ int carry;
    int tid = threadIdx.x;
    int lane = tid & 31, wid = tid >> 5;
    if (tid == 0) carry = 0;
    __syncthreads();
    for (int base = 0; base < NN; base += 1024) {
        int i = base + tid;
        int v = (i < NN) ? g_deg[i] : 0;
        int x = v;
        #pragma unroll
        for (int o = 1; o < 32; o <<= 1) {
            int y = __shfl_up_sync(0xffffffffu, x, o);
            if (lane >= o) x += y;
        }
        if (lane == 31) wsum[wid] = x;
        __syncthreads();
        if (wid == 0) {
            int s = wsum[lane];
            #pragma unroll
            for (int o = 1; o < 32; o <<= 1) {
                int y = __shfl_up_sync(0xffffffffu, s, o);
                if (lane >= o) s += y;
            }
            wsum[lane] = s;
        }
        __syncthreads();
        int pre = (wid > 0 ? wsum[wid-1] : 0) + carry;
        int incl = x + pre;
        if (i < NN) { g_offs[i] = incl - v; g_cursor[i] = incl - v; }
        __syncthreads();
        if (tid == 1023) carry = incl;
        __syncthreads();
    }
    if (tid == 0) g_offs[NN] = carry;
}

__global__ void scatter_kernel(const int* __restrict__ dst) {
    int e = blockIdx.x*blockDim.x + threadIdx.x;
    if (e < EE) {
        int p = atomicAdd(&g_cursor[dst[e]], 1);
        g_eidx[p] = e;
    }
}

__global__ void sort_kernel() {
    int n = blockIdx.x*blockDim.x + threadIdx.x;
    if (n >= NN) return;
    int a = g_offs[n], b = g_offs[n+1];
    for (int i = a+1; i < b; ++i) {
        int key = g_eidx[i];
        int j = i-1;
        while (j >= a && g_eidx[j] > key) { g_eidx[j+1] = g_eidx[j]; --j; }
        g_eidx[j+1] = key;
    }
}

// ---------------- layer-1 projections: half2-vectorized ----------------
__global__ void proj1_kernel(const float* __restrict__ x,
    const float* __restrict__ Wq, const float* __restrict__ bq,
    const float* __restrict__ Wk, const float* __restrict__ bk,
    const float* __restrict__ Wv, const float* __restrict__ bv,
    const float* __restrict__ Ws, const float* __restrict__ bs)
{
    int warp = (blockIdx.x*blockDim.x + threadIdx.x) >> 5;
    int lane = threadIdx.x & 31;
    if (warp >= NN) return;
    float xr[9];
    #pragma unroll
    for (int t = 0; t < 9; ++t) xr[t] = __ldg(&x[warp*9 + t]);
    #pragma unroll
    for (int j = lane*2; j < 512; j += 64) {
        float2 aq = __ldg((const float2*)&bq[j]);
        float2 ak = __ldg((const float2*)&bk[j]);
        float2 av = __ldg((const float2*)&bv[j]);
        float2 as_ = __ldg((const float2*)&bs[j]);
        #pragma unroll
        for (int t = 0; t < 9; ++t) {
            float xv = xr[t];
            float2 wq = __ldg((const float2*)&Wq[t*512+j]);
            float2 wk = __ldg((const float2*)&Wk[t*512+j]);
            float2 wv = __ldg((const float2*)&Wv[t*512+j]);
            float2 ws = __ldg((const float2*)&Ws[t*512+j]);
            aq.x = fmaf(xv, wq.x, aq.x);  aq.y = fmaf(xv, wq.y, aq.y);
            ak.x = fmaf(xv, wk.x, ak.x);  ak.y = fmaf(xv, wk.y, ak.y);
            av.x = fmaf(xv, wv.x, av.x);  av.y = fmaf(xv, wv.y, av.y);
            as_.x = fmaf(xv, ws.x, as_.x); as_.y = fmaf(xv, ws.y, as_.y);
        }
        size_t o = (size_t)warp*512 + j;
        *(__half2*)&g_q1h[o] = __floats2half2_rn(aq.x, aq.y);
        *(__half2*)&g_k1h[o] = __floats2half2_rn(ak.x, ak.y);
        *(__half2*)&g_v1h[o] = __floats2half2_rn(av.x, av.y);
        *(__half2*)&g_s1h[o] = __floats2half2_rn(as_.x, as_.y);
    }
}

// ---------------- layer-1 per-graph attention (graph offset) ----------------
__global__ void __launch_bounds__(640, 1) attn1_kernel(
    const __half* __restrict__ qh, const __half* __restrict__ khg,
    const __half* __restrict__ vhg, const __half* __restrict__ sh,
    const float* __restrict__ ea, const float* __restrict__ We,
    const int* __restrict__ srcArr, float* __restrict__ outPooled,
    __half* __restrict__ h1h, int goff)
{
    constexpr int D = 512, H = 4;
    constexpr int VPT = D / 32;
    constexpr int NU = VPT / 8;
    constexpr int C = D / H;
    extern __shared__ char smraw[];
    float*  sWeT = (float*)smraw;
    __half* kh   = (__half*)(smraw + 16*D);
    __half* vh   = (__half*)(smraw + 16*D + 40*D);
    float*  poolbuf = (float*)kh;

    int tid = threadIdx.x;
    int wid = tid >> 5, lane = tid & 31;
    int graph = blockIdx.x + goff;
    int gbase = graph * NPG;

    for (int i = tid; i < 4*D; i += 640) {
        int c = i >> 2, t = i & 3;
        sWeT[i] = __ldg(&We[t*D + c]);
    }
    {
        const uint4* ks = (const uint4*)(khg + (size_t)gbase*D);
        const uint4* vs = (const uint4*)(vhg + (size_t)gbase*D);
        uint4* kd = (uint4*)kh;
        uint4* vd = (uint4*)vh;
        for (int i = tid; i < NPG*D/8; i += 640) { kd[i] = __ldg(ks+i); vd[i] = __ldg(vs+i); }
    }
    __syncthreads();

    int node = gbase + wid;
    int cbase = lane * VPT;
    const float4* sWe4 = (const float4*)sWeT;

    float qrf[VPT], accf[VPT];
    {
        const uint4* q4 = (const uint4*)(qh + (size_t)node*D + cbase);
        #pragma unroll
        for (int i = 0; i < NU; ++i) {
            uint4 u = __ldg(q4 + i);
            const __half2* h2 = (const __half2*)&u;
            #pragma unroll
            for (int j = 0; j < 4; ++j) {
                float2 f = __half22float2(h2[j]);
                qrf[8*i+2*j] = f.x; qrf[8*i+2*j+1] = f.y;
            }
        }
    }
    #pragma unroll
    for (int i = 0; i < VPT; ++i) accf[i] = 0.f;

    float4 qe = make_float4(0.f,0.f,0.f,0.f);
    #pragma unroll
    for (int i = 0; i < VPT; ++i) {
        float4 w = sWe4[cbase + i];
        qe.x = fmaf(qrf[i], w.x, qe.x);
        qe.y = fmaf(qrf[i], w.y, qe.y);
        qe.z = fmaf(qrf[i], w.z, qe.z);
        qe.w = fmaf(qrf[i], w.w, qe.w);
    }
    #pragma unroll
    for (int o = 1; o < 8; o <<= 1) {
        qe.x += __shfl_xor_sync(0xffffffffu, qe.x, o);
        qe.y += __shfl_xor_sync(0xffffffffu, qe.y, o);
        qe.z += __shfl_xor_sync(0xffffffffu, qe.z, o);
        qe.w += __shfl_xor_sync(0xffffffffu, qe.w, o);
    }

    float m = -INFINITY, den = 0.f;
    float4 wa = make_float4(0.f,0.f,0.f,0.f);
    const float invs = rsqrtf((float)C);

    int e0 = g_offs[node], e1 = g_offs[node+1];
    for (int t = e0; t < e1; ++t) {
        int e  = __ldg(&g_eidx[t]);
        int ln = __ldg(&srcArr[e]) - gbase;
        float4 a4 = __ldg((const float4*)ea + e);

        const uint4* krow = (const uint4*)(kh + ln*D + cbase);
        float p = 0.f;
        #pragma unroll
        for (int i = 0; i < NU; ++i) {
            uint4 u = krow[i];
            const __half2* h2 = (const __half2*)&u;
            #pragma unroll
            for (int j = 0; j < 4; ++j) {
                float2 f = __half22float2(h2[j]);
                p = fmaf(qrf[8*i+2*j], f.x, p);
                p = fmaf(qrf[8*i+2*j+1], f.y, p);
            }
        }
        p += __shfl_xor_sync(0xffffffffu, p, 1);
        p += __shfl_xor_sync(0xffffffffu, p, 2);
        p += __shfl_xor_sync(0xffffffffu, p, 4);
        float alpha = (p + qe.x*a4.x + qe.y*a4.y + qe.z*a4.z + qe.w*a4.w) * invs;

        float nm = fmaxf(m, alpha);
        float sc = __expf(m - nm);
        float w  = __expf(alpha - nm);
        den = den*sc + w;
        m = nm;

        const uint4* vrow = (const uint4*)(vh + ln*D + cbase);
        #pragma unroll
        for (int i = 0; i < NU; ++i) {
            uint4 u = vrow[i];
            const __half2* h2 = (const __half2*)&u;
            #pragma unroll
            for (int j = 0; j < 4; ++j) {
                float2 f = __half22float2(h2[j]);
                accf[8*i+2*j]   = accf[8*i+2*j]*sc   + w*f.x;
                accf[8*i+2*j+1] = accf[8*i+2*j+1]*sc + w*f.y;
            }
        }
        wa.x = wa.x*sc + w*a4.x; wa.y = wa.y*sc + w*a4.y;
        wa.z = wa.z*sc + w*a4.z; wa.w = wa.w*sc + w*a4.w;
    }

    float r = 1.f / (den + 1e-16f);
    float outv[VPT];
    {
        const __half2* s2p = (const __half2*)(sh + (size_t)node*D + cbase);
        #pragma unroll
        for (int i = 0; i < VPT; ++i) {
            float4 w = sWe4[cbase + i];
            outv[i] = (accf[i] + wa.x*w.x + wa.y*w.y + wa.z*w.z + wa.w*w.w) * r;
        }
        #pragma unroll
        for (int i = 0; i < VPT/2; ++i) {
            float2 sv = __half22float2(__ldg(s2p + i));
            outv[2*i]   = fmaxf(outv[2*i]   + sv.x, 0.f);
            outv[2*i+1] = fmaxf(outv[2*i+1] + sv.y, 0.f);
        }
    }
    {
        __half2* h4 = (__half2*)(h1h + (size_t)node*D + cbase);
        #pragma unroll
        for (int i = 0; i < VPT/2; ++i)
            h4[i] = __floats2half2_rn(outv[2*i], outv[2*i+1]);
    }

    __syncthreads();
    #pragma unroll
    for (int i = 0; i < VPT; ++i) poolbuf[wid*D + cbase + i] = outv[i];
    __syncthreads();
    for (int c = tid; c < D; c += 640) {
        float sum = 0.f;
        #pragma unroll
        for (int i = 0; i < NPG; ++i) sum += poolbuf[i*D + c];
        outPooled[(size_t)graph*512 + c] = sum * (1.f/NPG);
    }
}

// ---------------- layer-2 attention: softmax weights only (graph offset) ----------------
__global__ void __launch_bounds__(640, 1) attn2_kernel(
    const __half* __restrict__ qh, const __half* __restrict__ khg,
    const __half* __restrict__ h1g,
    const float* __restrict__ ea, const float* __restrict__ We,
    const int* __restrict__ srcArr, int goff)
{
    constexpr int D = 1024, H = 4;
    constexpr int VPT = D / 32;
    constexpr int NU = VPT / 8;
    constexpr int C = D / H;
    constexpr int ECAP = 256;
    extern __shared__ char smraw[];
    float*  sWeT   = (float*)smraw;
    __half* kh     = (__half*)(smraw + 16*D);
    __half* h1s    = (__half*)(smraw + 16*D + 2*NPG*D);
    float*  alphaS = (float*)(smraw + 16*D + 2*NPG*D + NPG*1024);
    float*  wS     = alphaS + ECAP*H;
    int*    lnS    = (int*)(wS + ECAP*H);
    float*  cS     = (float*)(lnS + ECAP);
    int*    hasE   = (int*)(cS + NPG*H);

    int tid = threadIdx.x;
    int wid = tid >> 5, lane = tid & 31;
    int graph = blockIdx.x + goff;
    int gbase = graph * NPG;
    int head = lane >> 3;

    for (int i = tid; i < 4*D; i += 640) {
        int c = i >> 2, t = i & 3;
        sWeT[i] = __ldg(&We[t*D + c]);
    }
    {
        const uint4* ks = (const uint4*)(khg + (size_t)gbase*D);
        uint4* kd = (uint4*)kh;
        for (int i = tid; i < NPG*D/8; i += 640) kd[i] = __ldg(ks+i);
        const uint4* hs = (const uint4*)(h1g + (size_t)gbase*512);
        uint4* hd = (uint4*)h1s;
        for (int i = tid; i < NPG*512/8; i += 640) hd[i] = __ldg(hs+i);
    }
    __syncthreads();

    int node = gbase + wid;
    int cbase = lane * VPT;
    const float4* sWe4 = (const float4*)sWeT;

    float qrf[VPT];
    {
        const uint4* q4 = (const uint4*)(qh + (size_t)node*D + cbase);
        #pragma unroll
        for (int i = 0; i < NU; ++i) {
            uint4 u = __ldg(q4 + i);
            const __half2* h2 = (const __half2*)&u;
            #pragma unroll
            for (int j = 0; j < 4; ++j) {
                float2 f = __half22float2(h2[j]);
                qrf[8*i+2*j] = f.x; qrf[8*i+2*j+1] = f.y;
            }
        }
    }

    float4 qe = make_float4(0.f,0.f,0.f,0.f);
    #pragma unroll
    for (int i = 0; i < VPT; ++i) {
        float4 w = sWe4[cbase + i];
        qe.x = fmaf(qrf[i], w.x, qe.x);
        qe.y = fmaf(qrf[i], w.y, qe.y);
        qe.z = fmaf(qrf[i], w.z, qe.z);
        qe.w = fmaf(qrf[i], w.w, qe.w);
    }
    #pragma unroll
    for (int o = 1; o < 8; o <<= 1) {
        qe.x += __shfl_xor_sync(0xffffffffu, qe.x, o);
        qe.y += __shfl_xor_sync(0xffffffffu, qe.y, o);
        qe.z += __shfl_xor_sync(0xffffffffu, qe.z, o);
        qe.w += __shfl_xor_sync(0xffffffffu, qe.w, o);
    }

    const float invs = rsqrtf((float)C);
    int eb = g_offs[gbase];
    int cntE = g_offs[gbase + NPG] - eb;
    int e0 = g_offs[node], e1 = g_offs[node+1];

    float m = -INFINITY, den = 0.f;
    for (int t = e0; t < e1; ++t) {
        int e  = __ldg(&g_eidx[t]);
        int ln = __ldg(&srcArr[e]) - gbase;
        float4 a4 = __ldg((const float4*)ea + e);

        const uint4* krow = (const uint4*)(kh + ln*D + cbase);
        float p = 0.f;
        #pragma unroll
        for (int i = 0; i < NU; ++i) {
            uint4 u = krow[i];
            const __half2* h2 = (const __half2*)&u;
            #pragma unroll
            for (int j = 0; j < 4; ++j) {
                float2 f = __half22float2(h2[j]);
                p = fmaf(qrf[8*i+2*j], f.x, p);
                p = fmaf(qrf[8*i+2*j+1], f.y, p);
            }
        }
        p += __shfl_xor_sync(0xffffffffu, p, 1);
        p += __shfl_xor_sync(0xffffffffu, p, 2);
        p += __shfl_xor_sync(0xffffffffu, p, 4);
        float alpha = (p + qe.x*a4.x + qe.y*a4.y + qe.z*a4.z + qe.w*a4.w) * invs;

        float nm = fmaxf(m, alpha);
        den = den*__expf(m - nm) + __expf(alpha - nm);
        m = nm;
        if ((lane & 7) == 0) alphaS[(t - eb)*H + head] = alpha;
        if (lane == 0) lnS[t - eb] = ln;
    }
    float rdn = (e1 > e0) ? 1.f/den : 0.f;
    if ((lane & 7) == 0) {
        for (int t = e0; t < e1; ++t) {
            float w = __expf(alphaS[(t - eb)*H + head] - m) * rdn;
            wS[(t - eb)*H + head] = w;
        }
    }
    if (lane == 0) hasE[wid] = (e1 > e0) ? 1 : 0;
    __syncthreads();

    if (tid < NPG*H) {
        int ln = tid >> 2, h = tid & 3;
        float c = 0.f;
        for (int i = 0; i < cntE; ++i)
            if (lnS[i] == ln) c += wS[i*H + h];
        cS[tid] = c * (1.f/NPG);
    } else if (tid < NPG*H + 16) {
        int idx = tid - NPG*H;
        int h = idx >> 2, t4 = idx & 3;
        float r = 0.f;
        for (int i = 0; i < cntE; ++i) {
            int e = __ldg(&g_eidx[eb + i]);
            r += wS[i*H + h] * __ldg(&ea[e*4 + t4]);
        }
        g_r[graph*16 + h*4 + t4] = r * (1.f/NPG);
    } else if (tid == NPG*H + 16) {
        int c = 0;
        #pragma unroll
        for (int i = 0; i < NPG; ++i) c += hasE[i];
        g_cnt[graph] = (float)c;
    }
    __syncthreads();

    for (int o = tid; o < H*512; o += 640) {
        int h = o >> 9, c = o & 511;
        float z = 0.f;
        #pragma unroll
        for (int ln = 0; ln < NPG; ++ln)
            z = fmaf(cS[ln*H + h], __half2float(h1s[ln*512 + c]), z);
        g_z[(size_t)graph*2048 + o] = z;
    }
}

// ---------------- weight transpose+fp16 converts ----------------
__global__ void wt2half_kernel(const float* __restrict__ W0, const float* __restrict__ W1) {
    __shared__ float tile[32][33];
    int z = blockIdx.z;
    const float* W = (z==0) ? W0 : W1;
    int n0 = blockIdx.x * 32, k0 = blockIdx.y * 32;
    int tx = threadIdx.x, ty = threadIdx.y;
    tile[ty][tx] = __ldg(&W[(size_t)(k0+ty)*1024 + n0 + tx]);
    __syncthreads();
    g_w2h[(size_t)z*1024*512 + (size_t)(n0+ty)*512 + k0 + tx] = __float2half_rn(tile[tx][ty]);
}

__global__ void wfin2half_kernel(const float* __restrict__ W) {
    __shared__ float tile[32][33];
    int n0 = blockIdx.x * 32, k0 = blockIdx.y * 32;
    int tx = threadIdx.x, ty = threadIdx.y;
    tile[ty][tx] = __ldg(&W[(size_t)(k0+ty)*1024 + n0 + tx]);
    __syncthreads();
    g_wfinh[(size_t)(n0+ty)*1280 + k0 + tx] = __float2half_rn(tile[tx][ty]);
}

// ---------------- f16 tensor-core GEMM (M-block offset for chunking) ----------------
__global__ void __launch_bounds__(256, 2) gemm2_f16_kernel(
    const __half* __restrict__ Ah,
    const float* __restrict__ b0, const float* __restrict__ b1,
    int M, int mblk_off)
{
    __shared__ __align__(16) uint32_t As[3][128][20];
    __shared__ __align__(16) uint32_t Bs[3][128][20];

    int z = blockIdx.z;
    const __half* Bz  = g_w2h + (size_t)z*1024*512;
    const float* bias = (z==0) ? b0 : b1;
    __half* Ch = (z==0) ? g_q2h : g_k2h;

    int tid  = threadIdx.x;
    int lane = tid & 31, wid = tid >> 5;
    int wm = wid >> 2, wn = wid & 3;
    int m0 = (blockIdx.x + mblk_off) * 128, n0 = blockIdx.y * 128;
    int g = lane >> 2, t = lane & 3;

    int lm[2], lq[2];
    #pragma unroll
    for (int i = 0; i < 2; ++i) {
        int idx = tid + i*256;
        lm[i] = idx >> 2;
        lq[i] = (idx & 3) * 8;
    }

    float acc[4][4][4];
    #pragma unroll
    for (int a = 0; a < 4; ++a)
        #pragma unroll
        for (int b = 0; b < 4; ++b)
            #pragma unroll
            for (int c = 0; c < 4; ++c) acc[a][b][c] = 0.f;

    const int T = 512 / 32;

    #pragma unroll
    for (int pt = 0; pt < 2; ++pt) {
        int ko = pt * 32;
        #pragma unroll
        for (int i = 0; i < 2; ++i) {
            cpa16(&As[pt][lm[i]][lq[i]>>1],
                  Ah + (size_t)(m0+lm[i])*512 + ko + lq[i], (m0+lm[i]) < M);
            cpa16(&Bs[pt][lm[i]][lq[i]>>1],
                  Bz + (size_t)(n0+lm[i])*512 + ko + lq[i], true);
        }
        asm volatile("cp.async.commit_group;\n");
    }

    for (int kt = 0; kt < T; ++kt) {
        int sl = kt % 3;
        asm volatile("cp.async.wait_group 1;\n");
        __syncthreads();

        if (kt + 2 < T) {
            int ns = (kt + 2) % 3;
            int ko = (kt + 2) * 32;
            #pragma unroll
            for (int i = 0; i < 2; ++i) {
                cpa16(&As[ns][lm[i]][lq[i]>>1],
                      Ah + (size_t)(m0+lm[i])*512 + ko + lq[i], (m0+lm[i]) < M);
                cpa16(&Bs[ns][lm[i]][lq[i]>>1],
                      Bz + (size_t)(n0+lm[i])*512 + ko + lq[i], true);
            }
        }
        asm volatile("cp.async.commit_group;\n");

        #pragma unroll
        for (int ks = 0; ks < 2; ++ks) {
            int kb = ks * 8;
            uint32_t af[4][4], bf[4][2];
            #pragma unroll
            for (int mt = 0; mt < 4; ++mt) {
                int mb = wm*64 + mt*16;
                af[mt][0] = As[sl][mb+g  ][kb+t  ];
                af[mt][1] = As[sl][mb+g+8][kb+t  ];
                af[mt][2] = As[sl][mb+g  ][kb+t+4];
                af[mt][3] = As[sl][mb+g+8][kb+t+4];
            }
            #pragma unroll
            for (int nt = 0; nt < 4; ++nt) {
                int nb = wn*32 + nt*8;
                bf[nt][0] = Bs[sl][nb+g][kb+t  ];
                bf[nt][1] = Bs[sl][nb+g][kb+t+4];
            }
            #pragma unroll
            for (int mt = 0; mt < 4; ++mt)
                #pragma unroll
                for (int nt = 0; nt < 4; ++nt) {
                    asm volatile(
                        "mma.sync.aligned.m16n8k16.row.col.f32.f16.f16.f32 "
                        "{%0,%1,%2,%3}, {%4,%5,%6,%7}, {%8,%9}, {%0,%1,%2,%3};"
                        : "+f"(acc[mt][nt][0]), "+f"(acc[mt][nt][1]),
                          "+f"(acc[mt][nt][2]), "+f"(acc[mt][nt][3])
                        : "r"(af[mt][0]), "r"(af[mt][1]), "r"(af[mt][2]), "r"(af[mt][3]),
                          "r"(bf[nt][0]), "r"(bf[nt][1]));
                }
        }
    }

    #pragma unroll
    for (int mt = 0; mt < 4; ++mt) {
        int r0 = m0 + wm*64 + mt*16 + g;
        #pragma unroll
        for (int nt = 0; nt < 4; ++nt) {
            int c = n0 + wn*32 + nt*8 + t*2;
            float bv0 = __ldg(&bias[c]), bv1 = __ldg(&bias[c+1]);
            if (r0 < M)
                *(__half2*)&Ch[(size_t)r0*1024 + c] =
                    __floats2half2_rn(acc[mt][nt][0] + bv0, acc[mt][nt][1] + bv1);
            if (r0 + 8 < M)
                *(__half2*)&Ch[(size_t)(r0+8)*1024 + c] =
                    __floats2half2_rn(acc[mt][nt][2] + bv0, acc[mt][nt][3] + bv1);
        }
    }
}

// ---------------- final-GEMM f16 tensor kernel, split-K partials ----------------
__global__ void __launch_bounds__(256) gemmfin_f16_kernel(int M)
{
    __shared__ uint32_t As[2][128][20];
    __shared__ uint32_t Bs[2][128][20];

    int zs = blockIdx.z;
    int kbase = zs * 320;
    float* P = g_fpart + (size_t)zs*BB*1024;

    int tid  = threadIdx.x;
    int lane = tid & 31, wid = tid >> 5;
    int wm = wid >> 2, wn = wid & 3;
    int m0 = blockIdx.x * 128, n0 = blockIdx.y * 128;
    int g = lane >> 2, t = lane & 3;

    int lm[2], lq[2];
    #pragma unroll
    for (int i = 0; i < 2; ++i) {
        int idx = tid + i*256;
        lm[i] = idx >> 2;
        lq[i] = (idx & 3) * 8;
    }

    float acc[4][4][4];
    #pragma unroll
    for (int a = 0; a < 4; ++a)
        #pragma unroll
        for (int b = 0; b < 4; ++b)
            #pragma unroll
            for (int c = 0; c < 4; ++c) acc[a][b][c] = 0.f;

    float4 pa[2], pb[2];
    const int T = 10;

    #pragma unroll
    for (int i = 0; i < 2; ++i) {
        pa[i] = (m0 + lm[i] < M)
              ? *(const float4*)(g_cch + (size_t)(m0+lm[i])*1280 + kbase + lq[i])
              : make_float4(0.f,0.f,0.f,0.f);
        pb[i] = *(const float4*)(g_wfinh + (size_t)(n0+lm[i])*1280 + kbase + lq[i]);
    }
    #pragma unroll
    for (int i = 0; i < 2; ++i) {
        *(float4*)&As[0][lm[i]][lq[i]>>1] = pa[i];
        *(float4*)&Bs[0][lm[i]][lq[i]>>1] = pb[i];
    }
    __syncthreads();

    for (int kt = 0; kt < T; ++kt) {
        int b = kt & 1;
        if (kt + 1 < T) {
            int ko = kbase + (kt+1) * 32;
            #pragma unroll
            for (int i = 0; i < 2; ++i) {
                pa[i] = (m0 + lm[i] < M)
                      ? *(const float4*)(g_cch + (size_t)(m0+lm[i])*1280 + ko + lq[i])
                      : make_float4(0.f,0.f,0.f,0.f);
                pb[i] = *(const float4*)(g_wfinh + (size_t)(n0+lm[i])*1280 + ko + lq[i]);
            }
        }

        #pragma unroll
        for (int ks = 0; ks < 2; ++ks) {
            int kb = ks * 8;
            uint32_t af[4][4], bf[4][2];
            #pragma unroll
            for (int mt = 0; mt < 4; ++mt) {
                int mb = wm*64 + mt*16;
                af[mt][0] = As[b][mb+g  ][kb+t  ];
                af[mt][1] = As[b][mb+g+8][kb+t  ];
                af[mt][2] = As[b][mb+g  ][kb+t+4];
                af[mt][3] = As[b][mb+g+8][kb+t+4];
            }
            #pragma unroll
            for (int nt = 0; nt < 4; ++nt) {
                int nb = wn*32 + nt*8;
                bf[nt][0] = Bs[b][nb+g][kb+t  ];
                bf[nt][1] = Bs[b][nb+g][kb+t+4];
            }
            #pragma unroll
            for (int mt = 0; mt < 4; ++mt)
                #pragma unroll
                for (int nt = 0; nt < 4; ++nt) {
                    asm volatile(
                        "mma.sync.aligned.m16n8k16.row.col.f32.f16.f16.f32 "
                        "{%0,%1,%2,%3}, {%4,%5,%6,%7}, {%8,%9}, {%0,%1,%2,%3};"
                        : "+f"(acc[mt][nt][0]), "+f"(acc[mt][nt][1]),
                          "+f"(acc[mt][nt][2]), "+f"(acc[mt][nt][3])
                        : "r"(af[mt][0]), "r"(af[mt][1]), "r"(af[mt][2]), "r"(af[mt][3]),
                          "r"(bf[nt][0]), "r"(bf[nt][1]));
                }
        }

        if (kt + 1 < T) {
            int nb_ = b ^ 1;
            #pragma unroll
            for (int i = 0; i < 2; ++i) {
                *(float4*)&As[nb_][lm[i]][lq[i]>>1] = pa[i];
                *(float4*)&Bs[nb_][lm[i]][lq[i]>>1] = pb[i];
            }
            __syncthreads();
        }
    }

    #pragma unroll
    for (int mt = 0; mt < 4; ++mt) {
        int r0 = m0 + wm*64 + mt*16 + g;
        #pragma unroll
        for (int nt = 0; nt < 4; ++nt) {
            int c = n0 + wn*32 + nt*8 + t*2;
            if (r0 < M)
                *(float2*)&P[(size_t)r0*1024 + c] = make_float2(acc[mt][nt][0], acc[mt][nt][1]);
            if (r0 + 8 < M)
                *(float2*)&P[(size_t)(r0+8)*1024 + c] = make_float2(acc[mt][nt][2], acc[mt][nt][3]);
        }
    }
}

// ---------------- fp32 64x64 GEMM: pooled skip + z@Wv2 + edge/bias -> cch fp16 ------
__global__ void __launch_bounds__(256) gemm_pool64(
    const float* __restrict__ Ws2, const float* __restrict__ Wv2,
    const float* __restrict__ bs2,
    const float* __restrict__ We2, const float* __restrict__ bv2)
{
    __shared__ float As[16][68];
    __shared__ float Bs[16][68];
    int tid = threadIdx.x;
    int tx = tid & 15, ty = tid >> 4;
    int m0 = blockIdx.x * 64;
    int n0 = blockIdx.y * 64;
    int h = n0 >> 8;
    int hOff = h * 512;
    float acc[4][4] = {};

    int arow = tid >> 2, ac4 = (tid & 3)*4;
    int brow = tid >> 4, bc4 = (tid & 15)*4;

    #pragma unroll 1
    for (int half_ = 0; half_ < 2; ++half_) {
        const float* Bm = half_ ? Wv2 : Ws2;
        for (int k0 = 0; k0 < 512; k0 += 16) {
            float4 av = make_float4(0.f,0.f,0.f,0.f);
            if (m0 + arow < BB) {
                av = half_
                   ? __ldg((const float4*)&g_z[(size_t)(m0+arow)*2048 + hOff + k0 + ac4])
                   : __ldg((const float4*)&g_ph1[(size_t)(m0+arow)*512 + k0 + ac4]);
            }
            As[ac4+0][arow] = av.x; As[ac4+1][arow] = av.y;
            As[ac4+2][arow] = av.z; As[ac4+3][arow] = av.w;
            float4 bv = __ldg((const float4*)&Bm[(size_t)(k0+brow)*1024 + n0 + bc4]);
            *(float4*)&Bs[brow][bc4] = bv;
            __syncthreads();
            #pragma unroll
            for (int kk = 0; kk < 16; ++kk) {
                float a[4], b[4];
                *(float4*)a = *(const float4*)&As[kk][ty*4];
                *(float4*)b = *(const float4*)&Bs[kk][tx*4];
                #pragma unroll
                for (int i = 0; i < 4; ++i)
                    #pragma unroll
                    for (int j = 0; j < 4; ++j)
                        acc[i][j] = fmaf(a[i], b[j], acc[i][j]);
            }
            __syncthreads();
        }
    }
    #pragma unroll
    for (int i = 0; i < 4; ++i) {
        int row = m0 + ty*4 + i;
        if (row < BB) {
            float cfac = g_cnt[row] * (1.f/NPG);
            float r0 = g_r[row*16 + h*4 + 0], r1 = g_r[row*16 + h*4 + 1];
            float r2 = g_r[row*16 + h*4 + 2], r3 = g_r[row*16 + h*4 + 3];
            __half hbuf[4];
            #pragma unroll
            for (int j = 0; j < 4; ++j) {
                int col = n0 + tx*4 + j;
                float v = acc[i][j] + __ldg(&bs2[col]) + cfac*__ldg(&bv2[col]);
                v = fmaf(r0, __ldg(&We2[0*1024 + col]), v);
                v = fmaf(r1, __ldg(&We2[1*1024 + col]), v);
                v = fmaf(r2, __ldg(&We2[2*1024 + col]), v);
                v = fmaf(r3, __ldg(&We2[3*1024 + col]), v);
                hbuf[j] = __float2half_rn(v);
            }
            *(uint2*)&g_cch[(size_t)row*1280 + n0 + tx*4] = *(uint2*)hbuf;
        }
    }
}

// ---------------- fingerprint GEMM partials ----------------
__global__ void __launch_bounds__(256) gemm_fp64(
    const float* __restrict__ A, const float* __restrict__ Bm)
{
    __shared__ float As[16][68];
    __shared__ float Bs[16][68];
    int tid = threadIdx.x;
    int tx = tid & 15, ty = tid >> 4;
    int m0 = blockIdx.x * 64;
    int n0 = blockIdx.y * 64;
    int zs = blockIdx.z;
    int kb = zs * 512;
    float acc[4][4] = {};

    int arow = tid >> 2, ac4 = (tid & 3)*4;
    int brow = tid >> 4, bc4 = (tid & 15)*4;

    for (int k0 = kb; k0 < kb + 512; k0 += 16) {
        float4 av = make_float4(0.f,0.f,0.f,0.f);
        if (m0 + arow < BB)
            av = __ldg((const float4*)&A[(size_t)(m0+arow)*2048 + k0 + ac4]);
        As[ac4+0][arow] = av.x; As[ac4+1][arow] = av.y;
        As[ac4+2][arow] = av.z; As[ac4+3][arow] = av.w;
        float4 bv = __ldg((const float4*)&Bm[(size_t)(k0+brow)*256 + n0 + bc4]);
        *(float4*)&Bs[brow][bc4] = bv;
        __syncthreads();
        #pragma unroll
        for (int kk = 0; kk < 16; ++kk) {
            float a[4], b[4];
            *(float4*)a = *(const float4*)&As[kk][ty*4];
            *(float4*)b = *(const float4*)&Bs[kk][tx*4];
            #pragma unroll
            for (int i = 0; i < 4; ++i)
                #pragma unroll
                for (int j = 0; j < 4; ++j)
                    acc[i][j] = fmaf(a[i], b[j], acc[i][j]);
        }
        __syncthreads();
    }
    #pragma unroll
    for (int i = 0; i < 4; ++i) {
        int row = m0 + ty*4 + i;
        if (row < BB) {
            #pragma unroll
            for (int j = 0; j < 4; ++j) {
                int col = n0 + tx*4 + j;
                g_fppart[(size_t)zs*BB*256 + (size_t)row*256 + col] = acc[i][j];
            }
        }
    }
}

// ---------------- fingerprint cols -> cch fp16 ----------------
__global__ void fpcc_kernel(const float* __restrict__ bfp)
{
    int i = blockIdx.x*blockDim.x + threadIdx.x;
    if (i >= BB*128) return;
    int row = i >> 7;
    int cc = (i & 127) * 2;
    float v0 = __ldg(&bfp[cc]), v1 = __ldg(&bfp[cc+1]);
    #pragma unroll
    for (int zp = 0; zp < 4; ++zp) {
        v0 += g_fppart[(size_t)zp*BB*256 + (size_t)row*256 + cc];
        v1 += g_fppart[(size_t)zp*BB*256 + (size_t)row*256 + cc + 1];
    }
    *(__half2*)&g_cch[(size_t)row*1280 + 1024 + cc] = __floats2half2_rn(v0, v1);
}

// ---------------- final reduce ----------------
__global__ void reduce_fin_kernel(const float* __restrict__ bfin, float* __restrict__ out)
{
    int i = blockIdx.x*blockDim.x + threadIdx.x;
    if (i >= BB*256) return;
    int c4 = (i & 255) * 4;
    float4 acc = __ldg((const float4*)&bfin[c4]);
    #pragma unroll
    for (int zp = 0; zp < 4; ++zp) {
        float4 p = *(const float4*)&g_fpart[(size_t)zp*BB*1024 + (size_t)i*4];
        acc.x += p.x; acc.y += p.y; acc.z += p.z; acc.w += p.w;
    }
    ((float4*)out)[i] = acc;
}

// ---------------- launch ----------------
extern "C" void kernel_launch(void* const* d_in, const int* in_sizes, int n_in,
                              void* d_out, int out_size)
{
    const float* x    = (const float*)d_in[0];
    const int*   ei   = (const int*)  d_in[1];
    const float* ea   = (const float*)d_in[2];
    const float* fpb  = (const float*)d_in[4];
    const float *Wq1=(const float*)d_in[5],  *bq1=(const float*)d_in[6];
    const float *Wk1=(const float*)d_in[7],  *bk1=(const float*)d_in[8];
    const float *Wv1=(const float*)d_in[9],  *bv1=(const float*)d_in[10];
    const float *We1=(const float*)d_in[11];
    const float *Ws1=(const float*)d_in[12], *bs1=(const float*)d_in[13];
    const float *Wq2=(const float*)d_in[14], *bq2=(const float*)d_in[15];
    const float *Wk2=(const float*)d_in[16], *bk2=(const float*)d_in[17];
    const float *Wv2=(const float*)d_in[18], *bv2=(const float*)d_in[19];
    const float *We2=(const float*)d_in[20];
    const float *Ws2=(const float*)d_in[21], *bs2=(const float*)d_in[22];
    const float *Wfp=(const float*)d_in[23], *bfp=(const float*)d_in[24];
    const float *Wfin=(const float*)d_in[25],*bfin=(const float*)d_in[26];

    const int* srcArr = ei;
    const int* dstArr = ei + EE;

    float *ph1;
    __half *q1h,*s1h,*k1h,*v1h,*h1h,*q2h,*k2h;
    cudaGetSymbolAddress((void**)&q1h, g_q1h);
    cudaGetSymbolAddress((void**)&s1h, g_s1h);
    cudaGetSymbolAddress((void**)&k1h, g_k1h);
    cudaGetSymbolAddress((void**)&v1h, g_v1h);
    cudaGetSymbolAddress((void**)&h1h, g_h1h);
    cudaGetSymbolAddress((void**)&ph1, g_ph1);
    cudaGetSymbolAddress((void**)&q2h, g_q2h);
    cudaGetSymbolAddress((void**)&k2h, g_k2h);

    const int SM1 = 96*512;
    const int SM2 = 16*1024 + 2*NPG*1024 + NPG*1024
                  + 256*4*4*2 + 256*4 + NPG*4*4 + NPG*4 + 64;
    cudaFuncSetAttribute(attn1_kernel, cudaFuncAttributeMaxDynamicSharedMemorySize, SM1);
    cudaFuncSetAttribute(attn2_kernel, cudaFuncAttributeMaxDynamicSharedMemorySize, SM2);

    // Chunk boundary aligned to BOTH graph size (20) and GEMM M-tile (128):
    // 608 graphs = 12160 rows = 95 * 128 exactly.
    const int GH0  = 608;            // chunk0 graphs
    const int GH1  = BB - GH0;       // 592
    const int MBLK = 188;            // total 128-row blocks (24064 >= 24000)
    const int MB0  = 95;             // chunk0 covers rows [0, 12160) == attn1 chunk0 output

    // ---- fork side stream ----
    cudaEventRecord(g_evA0, 0);
    cudaStreamWaitEvent(g_sB, g_evA0, 0);

    // side: CSR -> wt2half -> fp path
    zero_deg_kernel<<<(NN+255)/256, 256, 0, g_sB>>>();
    hist_kernel<<<(EE+255)/256, 256, 0, g_sB>>>(dstArr);
    scan_kernel<<<1, 1024, 0, g_sB>>>();
    scatter_kernel<<<(EE+255)/256, 256, 0, g_sB>>>(dstArr);
    sort_kernel<<<(NN+255)/256, 256, 0, g_sB>>>();
    cudaEventRecord(g_evCSR, g_sB);
    wt2half_kernel<<<dim3(32, 16, 2), dim3(32, 32), 0, g_sB>>>(Wq2, Wk2);
    cudaEventRecord(g_evB1, g_sB);
    wfin2half_kernel<<<dim3(32, 40), dim3(32, 32), 0, g_sB>>>(Wfin);
    gemm_fp64<<<dim3((BB+63)/64, 4, 4), 256, 0, g_sB>>>(fpb, Wfp);
    fpcc_kernel<<<(BB*128+255)/256, 256, 0, g_sB>>>(bfp);
    cudaEventRecord(g_evB2, g_sB);

    // main: proj1
    proj1_kernel<<<(NN*32+255)/256, 256>>>(x, Wq1,bq1, Wk1,bk1, Wv1,bv1, Ws1,bs1);
    cudaEventRecord(g_evProj, 0);

    // main: attn1 chunk0 (graphs 0..607 -> h1h rows [0, 12160))
    cudaStreamWaitEvent(0, g_evCSR, 0);
    attn1_kernel<<<GH0, 640, SM1>>>(q1h, k1h, v1h, s1h, ea, We1, srcArr, ph1, h1h, 0);

    // side: attn1 chunk1 (graphs 608..1199) after proj1 (+ CSR, fp path in-stream)
    cudaStreamWaitEvent(g_sB, g_evProj, 0);
    attn1_kernel<<<GH1, 640, SM1, g_sB>>>(q1h, k1h, v1h, s1h, ea, We1, srcArr, ph1, h1h, GH0);
    cudaEventRecord(g_evH1, g_sB);

    // main: gemm2 chunk0 (rows [0, 12160)), needs wt2half + attn1 chunk0 (in-stream)
    cudaStreamWaitEvent(0, g_evB1, 0);
    gemm2_f16_kernel<<<dim3(MB0, 1024/128, 2), 256>>>(h1h, bq2, bk2, NN, 0);
    cudaEventRecord(g_evG0, 0);

    // main: gemm2 chunk1 (rows [12160, 24000)), needs attn1 chunk1
    cudaStreamWaitEvent(0, g_evH1, 0);
    gemm2_f16_kernel<<<dim3(MBLK-MB0, 1024/128, 2), 256>>>(h1h, bq2, bk2, NN, MB0);

    // side: attn2 chunk0 (graphs 0..607, reads q2/k2 rows < 12160) overlaps gemm2 chunk1
    cudaStreamWaitEvent(g_sB, g_evG0, 0);
    attn2_kernel<<<GH0, 640, SM2, g_sB>>>(q2h, k2h, h1h, ea, We2, srcArr, 0);
    cudaEventRecord(g_evZ0, g_sB);

    // main: attn2 chunk1 (graphs 608..1199)
    attn2_kernel<<<GH1, 640, SM2>>>(q2h, k2h, h1h, ea, We2, srcArr, GH0);

    // main: pool64 (z chunk0 via evZ0; z chunk1 + ph1 in-stream)
    cudaStreamWaitEvent(0, g_evZ0, 0);
    gemm_pool64<<<dim3((BB+63)/64, 1024/64), 256>>>(Ws2, Wv2, bs2, We2, bv2);

    // main: final GEMM (wfinh + fpcc via evB2)
    cudaStreamWaitEvent(0, g_evB2, 0);
    gemmfin_f16_kernel<<<dim3((BB+127)/128, 1024/128, 4), 256>>>(BB);
    reduce_fin_kernel<<<(BB*256+255)/256, 256>>>(bfin, (float*)d_out);
}

// round 16
// speedup vs baseline: 1.0508x; 1.0508x over previous
#include <cuda_runtime.h>
#include <cuda_fp16.h>
#include <math.h>
#include <stdint.h>

#define NN 24000
#define EE 96000
#define BB 1200
#define NPG 20

// ---------------- device scratch ----------------
__device__ __half g_q1h[NN*512];
__device__ __half g_s1h[NN*512];
__device__ __half g_k1h[NN*512];
__device__ __half g_v1h[NN*512];
__device__ __half g_h1h[NN*512];
__device__ float  g_ph1[BB*512];
__device__ __half g_q2h[NN*1024];
__device__ __half g_k2h[NN*1024];
__device__ float  g_z[BB*2048];
__device__ float  g_r[BB*16];
__device__ float  g_cnt[BB];
__device__ int    g_deg[NN];
__device__ int    g_offs[NN+1];
__device__ int    g_cursor[NN];
__device__ int    g_eidx[EE];
__device__ __half g_w2h[2*1024*512];
__device__ __half g_wfinh[1024*1280];
__device__ __half g_cch[BB*1280];
__device__ float  g_fppart[4*BB*256];
__device__ float  g_fpart[4*BB*1024];

// ---------------- side stream + events ----------------
static cudaStream_t g_sB;
static cudaEvent_t  g_evA0, g_evCSR, g_evB1, g_evB2;
namespace {
struct StreamInit {
    StreamInit() {
        cudaStreamCreateWithFlags(&g_sB, cudaStreamNonBlocking);
        cudaEventCreateWithFlags(&g_evA0,  cudaEventDisableTiming);
        cudaEventCreateWithFlags(&g_evCSR, cudaEventDisableTiming);
        cudaEventCreateWithFlags(&g_evB1,  cudaEventDisableTiming);
        cudaEventCreateWithFlags(&g_evB2,  cudaEventDisableTiming);
    }
};
static StreamInit g_streamInit;
}

__device__ __forceinline__ void cpa16(void* dst, const void* src, bool pred) {
    uint32_t d = (uint32_t)__cvta_generic_to_shared(dst);
    int sz = pred ? 16 : 0;
    asm volatile("cp.async.cg.shared.global [%0], [%1], 16, %2;\n"
                 :: "r"(d), "l"(src), "r"(sz));
}

// ---------------- CSR build ----------------
__global__ void zero_deg_kernel() {
    int i = blockIdx.x*blockDim.x + threadIdx.x;
    if (i < NN) g_deg[i] = 0;
}

__global__ void hist_kernel(const int* __restrict__ dst) {
    int e = blockIdx.x*blockDim.x + threadIdx.x;
    if (e < EE) atomicAdd(&g_deg[dst[e]], 1);
}

__global__ void scan_kernel() {
    __shared__ int wsum[32];
    __shared__ int carry;
    int tid = threadIdx.x;
    int lane = tid & 31, wid = tid >> 5;
    if (tid == 0) carry = 0;
    __syncthreads();
    for (int base = 0; base < NN; base += 1024) {
        int i = base + tid;
        int v = (i < NN) ? g_deg[i] : 0;
        int x = v;
        #pragma unroll
        for (int o = 1; o < 32; o <<= 1) {
            int y = __shfl_up_sync(0xffffffffu, x, o);
            if (lane >= o) x += y;
        }
        if (lane == 31) wsum[wid] = x;
        __syncthreads();
        if (wid == 0) {
            int s = wsum[lane];
            #pragma unroll
            for (int o = 1; o < 32; o <<= 1) {
                int y = __shfl_up_sync(0xffffffffu, s, o);
                if (lane >= o) s += y;
            }
            wsum[lane] = s;
        }
        __syncthreads();
        int pre = (wid > 0 ? wsum[wid-1] : 0) + carry;
        int incl = x + pre;
        if (i < NN) { g_offs[i] = incl - v; g_cursor[i] = incl - v; }
        __syncthreads();
        if (tid == 1023) carry = incl;
        __syncthreads();
    }
    if (tid == 0) g_offs[NN] = carry;
}

__global__ void scatter_kernel(const int* __restrict__ dst) {
    int e = blockIdx.x*blockDim.x + threadIdx.x;
    if (e < EE) {
        int p = atomicAdd(&g_cursor[dst[e]], 1);
        g_eidx[p] = e;
    }
}

__global__ void sort_kernel() {
    int n = blockIdx.x*blockDim.x + threadIdx.x;
    if (n >= NN) return;
    int a = g_offs[n], b = g_offs[n+1];
    for (int i = a+1; i < b; ++i) {
        int key = g_eidx[i];
        int j = i-1;
        while (j >= a && g_eidx[j] > key) { g_eidx[j+1] = g_eidx[j]; --j; }
        g_eidx[j+1] = key;
    }
}

// ---------------- layer-1 projections: half2-vectorized ----------------
__global__ void proj1_kernel(const float* __restrict__ x,
    const float* __restrict__ Wq, const float* __restrict__ bq,
    const float* __restrict__ Wk, const float* __restrict__ bk,
    const float* __restrict__ Wv, const float* __restrict__ bv,
    const float* __restrict__ Ws, const float* __restrict__ bs)
{
    int warp = (blockIdx.x*blockDim.x + threadIdx.x) >> 5;
    int lane = threadIdx.x & 31;
    if (warp >= NN) return;
    float xr[9];
    #pragma unroll
    for (int t = 0; t < 9; ++t) xr[t] = __ldg(&x[warp*9 + t]);
    #pragma unroll
    for (int j = lane*2; j < 512; j += 64) {
        float2 aq = __ldg((const float2*)&bq[j]);
        float2 ak = __ldg((const float2*)&bk[j]);
        float2 av = __ldg((const float2*)&bv[j]);
        float2 as_ = __ldg((const float2*)&bs[j]);
        #pragma unroll
        for (int t = 0; t < 9; ++t) {
            float xv = xr[t];
            float2 wq = __ldg((const float2*)&Wq[t*512+j]);
            float2 wk = __ldg((const float2*)&Wk[t*512+j]);
            float2 wv = __ldg((const float2*)&Wv[t*512+j]);
            float2 ws = __ldg((const float2*)&Ws[t*512+j]);
            aq.x = fmaf(xv, wq.x, aq.x);  aq.y = fmaf(xv, wq.y, aq.y);
            ak.x = fmaf(xv, wk.x, ak.x);  ak.y = fmaf(xv, wk.y, ak.y);
            av.x = fmaf(xv, wv.x, av.x);  av.y = fmaf(xv, wv.y, av.y);
            as_.x = fmaf(xv, ws.x, as_.x); as_.y = fmaf(xv, ws.y, as_.y);
        }
        size_t o = (size_t)warp*512 + j;
        *(__half2*)&g_q1h[o] = __floats2half2_rn(aq.x, aq.y);
        *(__half2*)&g_k1h[o] = __floats2half2_rn(ak.x, ak.y);
        *(__half2*)&g_v1h[o] = __floats2half2_rn(av.x, av.y);
        *(__half2*)&g_s1h[o] = __floats2half2_rn(as_.x, as_.y);
    }
}

// ---------------- layer-1 per-graph attention ----------------
__global__ void __launch_bounds__(640, 1) attn1_kernel(
    const __half* __restrict__ qh, const __half* __restrict__ khg,
    const __half* __restrict__ vhg, const __half* __restrict__ sh,
    const float* __restrict__ ea, const float* __restrict__ We,
    const int* __restrict__ srcArr, float* __restrict__ outPooled,
    __half* __restrict__ h1h)
{
    constexpr int D = 512, H = 4;
    constexpr int VPT = D / 32;
    constexpr int NU = VPT / 8;
    constexpr int C = D / H;
    extern __shared__ char smraw[];
    float*  sWeT = (float*)smraw;
    __half* kh   = (__half*)(smraw + 16*D);
    __half* vh   = (__half*)(smraw + 16*D + 40*D);
    float*  poolbuf = (float*)kh;

    int tid = threadIdx.x;
    int wid = tid >> 5, lane = tid & 31;
    int graph = blockIdx.x;
    int gbase = graph * NPG;

    for (int i = tid; i < 4*D; i += 640) {
        int c = i >> 2, t = i & 3;
        sWeT[i] = __ldg(&We[t*D + c]);
    }
    {
        const uint4* ks = (const uint4*)(khg + (size_t)gbase*D);
        const uint4* vs = (const uint4*)(vhg + (size_t)gbase*D);
        uint4* kd = (uint4*)kh;
        uint4* vd = (uint4*)vh;
        for (int i = tid; i < NPG*D/8; i += 640) { kd[i] = __ldg(ks+i); vd[i] = __ldg(vs+i); }
    }
    __syncthreads();

    int node = gbase + wid;
    int cbase = lane * VPT;
    const float4* sWe4 = (const float4*)sWeT;

    float qrf[VPT], accf[VPT];
    {
        const uint4* q4 = (const uint4*)(qh + (size_t)node*D + cbase);
        #pragma unroll
        for (int i = 0; i < NU; ++i) {
            uint4 u = __ldg(q4 + i);
            const __half2* h2 = (const __half2*)&u;
            #pragma unroll
            for (int j = 0; j < 4; ++j) {
                float2 f = __half22float2(h2[j]);
                qrf[8*i+2*j] = f.x; qrf[8*i+2*j+1] = f.y;
            }
        }
    }
    #pragma unroll
    for (int i = 0; i < VPT; ++i) accf[i] = 0.f;

    float4 qe = make_float4(0.f,0.f,0.f,0.f);
    #pragma unroll
    for (int i = 0; i < VPT; ++i) {
        float4 w = sWe4[cbase + i];
        qe.x = fmaf(qrf[i], w.x, qe.x);
        qe.y = fmaf(qrf[i], w.y, qe.y);
        qe.z = fmaf(qrf[i], w.z, qe.z);
        qe.w = fmaf(qrf[i], w.w, qe.w);
    }
    #pragma unroll
    for (int o = 1; o < 8; o <<= 1) {
        qe.x += __shfl_xor_sync(0xffffffffu, qe.x, o);
        qe.y += __shfl_xor_sync(0xffffffffu, qe.y, o);
        qe.z += __shfl_xor_sync(0xffffffffu, qe.z, o);
        qe.w += __shfl_xor_sync(0xffffffffu, qe.w, o);
    }

    float m = -INFINITY, den = 0.f;
    float4 wa = make_float4(0.f,0.f,0.f,0.f);
    const float invs = rsqrtf((float)C);

    int e0 = g_offs[node], e1 = g_offs[node+1];
    for (int t = e0; t < e1; ++t) {
        int e  = __ldg(&g_eidx[t]);
        int ln = __ldg(&srcArr[e]) - gbase;
        float4 a4 = __ldg((const float4*)ea + e);

        const uint4* krow = (const uint4*)(kh + ln*D + cbase);
        float p = 0.f;
        #pragma unroll
        for (int i = 0; i < NU; ++i) {
            uint4 u = krow[i];
            const __half2* h2 = (const __half2*)&u;
            #pragma unroll
            for (int j = 0; j < 4; ++j) {
                float2 f = __half22float2(h2[j]);
                p = fmaf(qrf[8*i+2*j], f.x, p);
                p = fmaf(qrf[8*i+2*j+1], f.y, p);
            }
        }
        p += __shfl_xor_sync(0xffffffffu, p, 1);
        p += __shfl_xor_sync(0xffffffffu, p, 2);
        p += __shfl_xor_sync(0xffffffffu, p, 4);
        float alpha = (p + qe.x*a4.x + qe.y*a4.y + qe.z*a4.z + qe.w*a4.w) * invs;

        float nm = fmaxf(m, alpha);
        float sc = __expf(m - nm);
        float w  = __expf(alpha - nm);
        den = den*sc + w;
        m = nm;

        const uint4* vrow = (const uint4*)(vh + ln*D + cbase);
        #pragma unroll
        for (int i = 0; i < NU; ++i) {
            uint4 u = vrow[i];
            const __half2* h2 = (const __half2*)&u;
            #pragma unroll
            for (int j = 0; j < 4; ++j) {
                float2 f = __half22float2(h2[j]);
                accf[8*i+2*j]   = accf[8*i+2*j]*sc   + w*f.x;
                accf[8*i+2*j+1] = accf[8*i+2*j+1]*sc + w*f.y;
            }
        }
        wa.x = wa.x*sc + w*a4.x; wa.y = wa.y*sc + w*a4.y;
        wa.z = wa.z*sc + w*a4.z; wa.w = wa.w*sc + w*a4.w;
    }

    float r = 1.f / (den + 1e-16f);
    float outv[VPT];
    {
        const __half2* s2p = (const __half2*)(sh + (size_t)node*D + cbase);
        #pragma unroll
        for (int i = 0; i < VPT; ++i) {
            float4 w = sWe4[cbase + i];
            outv[i] = (accf[i] + wa.x*w.x + wa.y*w.y + wa.z*w.z + wa.w*w.w) * r;
        }
        #pragma unroll
        for (int i = 0; i < VPT/2; ++i) {
            float2 sv = __half22float2(__ldg(s2p + i));
            outv[2*i]   = fmaxf(outv[2*i]   + sv.x, 0.f);
            outv[2*i+1] = fmaxf(outv[2*i+1] + sv.y, 0.f);
        }
    }
    {
        __half2* h4 = (__half2*)(h1h + (size_t)node*D + cbase);
        #pragma unroll
        for (int i = 0; i < VPT/2; ++i)
            h4[i] = __floats2half2_rn(outv[2*i], outv[2*i+1]);
    }

    __syncthreads();
    #pragma unroll
    for (int i = 0; i < VPT; ++i) poolbuf[wid*D + cbase + i] = outv[i];
    __syncthreads();
    for (int c = tid; c < D; c += 640) {
        float sum = 0.f;
        #pragma unroll
        for (int i = 0; i < NPG; ++i) sum += poolbuf[i*D + c];
        outPooled[(size_t)graph*512 + c] = sum * (1.f/NPG);
    }
}

// ---------------- layer-2 attention: softmax weights only ----------------
__global__ void __launch_bounds__(640, 1) attn2_kernel(
    const __half* __restrict__ qh, const __half* __restrict__ khg,
    const __half* __restrict__ h1g,
    const float* __restrict__ ea, const float* __restrict__ We,
    const int* __restrict__ srcArr)
{
    constexpr int D = 1024, H = 4;
    constexpr int VPT = D / 32;
    constexpr int NU = VPT / 8;
    constexpr int C = D / H;
    constexpr int ECAP = 256;
    extern __shared__ char smraw[];
    float*  sWeT   = (float*)smraw;
    __half* kh     = (__half*)(smraw + 16*D);
    __half* h1s    = (__half*)(smraw + 16*D + 2*NPG*D);
    float*  alphaS = (float*)(smraw + 16*D + 2*NPG*D + NPG*1024);
    float*  wS     = alphaS + ECAP*H;
    int*    lnS    = (int*)(wS + ECAP*H);
    float*  cS     = (float*)(lnS + ECAP);
    int*    hasE   = (int*)(cS + NPG*H);

    int tid = threadIdx.x;
    int wid = tid >> 5, lane = tid & 31;
    int graph = blockIdx.x;
    int gbase = graph * NPG;
    int head = lane >> 3;

    for (int i = tid; i < 4*D; i += 640) {
        int c = i >> 2, t = i & 3;
        sWeT[i] = __ldg(&We[t*D + c]);
    }
    {
        const uint4* ks = (const uint4*)(khg + (size_t)gbase*D);
        uint4* kd = (uint4*)kh;
        for (int i = tid; i < NPG*D/8; i += 640) kd[i] = __ldg(ks+i);
        const uint4* hs = (const uint4*)(h1g + (size_t)gbase*512);
        uint4* hd = (uint4*)h1s;
        for (int i = tid; i < NPG*512/8; i += 640) hd[i] = __ldg(hs+i);
    }
    __syncthreads();

    int node = gbase + wid;
    int cbase = lane * VPT;
    const float4* sWe4 = (const float4*)sWeT;

    float qrf[VPT];
    {
        const uint4* q4 = (const uint4*)(qh + (size_t)node*D + cbase);
        #pragma unroll
        for (int i = 0; i < NU; ++i) {
            uint4 u = __ldg(q4 + i);
            const __half2* h2 = (const __half2*)&u;
            #pragma unroll
            for (int j = 0; j < 4; ++j) {
                float2 f = __half22float2(h2[j]);
                qrf[8*i+2*j] = f.x; qrf[8*i+2*j+1] = f.y;
            }
        }
    }

    float4 qe = make_float4(0.f,0.f,0.f,0.f);
    #pragma unroll
    for (int i = 0; i < VPT; ++i) {
        float4 w = sWe4[cbase + i];
        qe.x = fmaf(qrf[i], w.x, qe.x);
        qe.y = fmaf(qrf[i], w.y, qe.y);
        qe.z = fmaf(qrf[i], w.z, qe.z);
        qe.w = fmaf(qrf[i], w.w, qe.w);
    }
    #pragma unroll
    for (int o = 1; o < 8; o <<= 1) {
        qe.x += __shfl_xor_sync(0xffffffffu, qe.x, o);
        qe.y += __shfl_xor_sync(0xffffffffu, qe.y, o);
        qe.z += __shfl_xor_sync(0xffffffffu, qe.z, o);
        qe.w += __shfl_xor_sync(0xffffffffu, qe.w, o);
    }

    const float invs = rsqrtf((float)C);
    int eb = g_offs[gbase];
    int cntE = g_offs[gbase + NPG] - eb;
    int e0 = g_offs[node], e1 = g_offs[node+1];

    float m = -INFINITY, den = 0.f;
    for (int t = e0; t < e1; ++t) {
        int e  = __ldg(&g_eidx[t]);
        int ln = __ldg(&srcArr[e]) - gbase;
        float4 a4 = __ldg((const float4*)ea + e);

        const uint4* krow = (const uint4*)(kh + ln*D + cbase);
        float p = 0.f;
        #pragma unroll
        for (int i = 0; i < NU; ++i) {
            uint4 u = krow[i];
            const __half2* h2 = (const __half2*)&u;
            #pragma unroll
            for (int j = 0; j < 4; ++j) {
                float2 f = __half22float2(h2[j]);
                p = fmaf(qrf[8*i+2*j], f.x, p);
                p = fmaf(qrf[8*i+2*j+1], f.y, p);
            }
        }
        p += __shfl_xor_sync(0xffffffffu, p, 1);
        p += __shfl_xor_sync(0xffffffffu, p, 2);
        p += __shfl_xor_sync(0xffffffffu, p, 4);
        float alpha = (p + qe.x*a4.x + qe.y*a4.y + qe.z*a4.z + qe.w*a4.w) * invs;

        float nm = fmaxf(m, alpha);
        den = den*__expf(m - nm) + __expf(alpha - nm);
        m = nm;
        if ((lane & 7) == 0) alphaS[(t - eb)*H + head] = alpha;
        if (lane == 0) lnS[t - eb] = ln;
    }
    float rdn = (e1 > e0) ? 1.f/den : 0.f;
    if ((lane & 7) == 0) {
        for (int t = e0; t < e1; ++t) {
            float w = __expf(alphaS[(t - eb)*H + head] - m) * rdn;
            wS[(t - eb)*H + head] = w;
        }
    }
    if (lane == 0) hasE[wid] = (e1 > e0) ? 1 : 0;
    __syncthreads();

    if (tid < NPG*H) {
        int ln = tid >> 2, h = tid & 3;
        float c = 0.f;
        for (int i = 0; i < cntE; ++i)
            if (lnS[i] == ln) c += wS[i*H + h];
        cS[tid] = c * (1.f/NPG);
    } else if (tid < NPG*H + 16) {
        int idx = tid - NPG*H;
        int h = idx >> 2, t4 = idx & 3;
        float r = 0.f;
        for (int i = 0; i < cntE; ++i) {
            int e = __ldg(&g_eidx[eb + i]);
            r += wS[i*H + h] * __ldg(&ea[e*4 + t4]);
        }
        g_r[graph*16 + h*4 + t4] = r * (1.f/NPG);
    } else if (tid == NPG*H + 16) {
        int c = 0;
        #pragma unroll
        for (int i = 0; i < NPG; ++i) c += hasE[i];
        g_cnt[graph] = (float)c;
    }
    __syncthreads();

    for (int o = tid; o < H*512; o += 640) {
        int h = o >> 9, c = o & 511;
        float z = 0.f;
        #pragma unroll
        for (int ln = 0; ln < NPG; ++ln)
            z = fmaf(cS[ln*H + h], __half2float(h1s[ln*512 + c]), z);
        g_z[(size_t)graph*2048 + o] = z;
    }
}

// ---------------- weight transpose+fp16 converts ----------------
__global__ void wt2half_kernel(const float* __restrict__ W0, const float* __restrict__ W1) {
    __shared__ float tile[32][33];
    int z = blockIdx.z;
    const float* W = (z==0) ? W0 : W1;
    int n0 = blockIdx.x * 32, k0 = blockIdx.y * 32;
    int tx = threadIdx.x, ty = threadIdx.y;
    tile[ty][tx] = __ldg(&W[(size_t)(k0+ty)*1024 + n0 + tx]);
    __syncthreads();
    g_w2h[(size_t)z*1024*512 + (size_t)(n0+ty)*512 + k0 + tx] = __float2half_rn(tile[tx][ty]);
}

__global__ void wfin2half_kernel(const float* __restrict__ W) {
    __shared__ float tile[32][33];
    int n0 = blockIdx.x * 32, k0 = blockIdx.y * 32;
    int tx = threadIdx.x, ty = threadIdx.y;
    tile[ty][tx] = __ldg(&W[(size_t)(k0+ty)*1024 + n0 + tx]);
    __syncthreads();
    g_wfinh[(size_t)(n0+ty)*1280 + k0 + tx] = __float2half_rn(tile[tx][ty]);
}

// ---------------- f16 tensor-core GEMM ----------------
__global__ void __launch_bounds__(256, 2) gemm2_f16_kernel(
    const __half* __restrict__ Ah,
    const float* __restrict__ b0, const float* __restrict__ b1,
    int M)
{
    __shared__ __align__(16) uint32_t As[3][128][20];
    __shared__ __align__(16) uint32_t Bs[3][128][20];

    int z = blockIdx.z;
    const __half* Bz  = g_w2h + (size_t)z*1024*512;
    const float* bias = (z==0) ? b0 : b1;
    __half* Ch = (z==0) ? g_q2h : g_k2h;

    int tid  = threadIdx.x;
    int lane = tid & 31, wid = tid >> 5;
    int wm = wid >> 2, wn = wid & 3;
    int m0 = blockIdx.x * 128, n0 = blockIdx.y * 128;
    int g = lane >> 2, t = lane & 3;

    int lm[2], lq[2];
    #pragma unroll
    for (int i = 0; i < 2; ++i) {
        int idx = tid + i*256;
        lm[i] = idx >> 2;
        lq[i] = (idx & 3) * 8;
    }

    float acc[4][4][4];
    #pragma unroll
    for (int a = 0; a < 4; ++a)
        #pragma unroll
        for (int b = 0; b < 4; ++b)
            #pragma unroll
            for (int c = 0; c < 4; ++c) acc[a][b][c] = 0.f;

    const int T = 512 / 32;

    #pragma unroll
    for (int pt = 0; pt < 2; ++pt) {
        int ko = pt * 32;
        #pragma unroll
        for (int i = 0; i < 2; ++i) {
            cpa16(&As[pt][lm[i]][lq[i]>>1],
                  Ah + (size_t)(m0+lm[i])*512 + ko + lq[i], (m0+lm[i]) < M);
            cpa16(&Bs[pt][lm[i]][lq[i]>>1],
                  Bz + (size_t)(n0+lm[i])*512 + ko + lq[i], true);
        }
        asm volatile("cp.async.commit_group;\n");
    }

    for (int kt = 0; kt < T; ++kt) {
        int sl = kt % 3;
        asm volatile("cp.async.wait_group 1;\n");
        __syncthreads();

        if (kt + 2 < T) {
            int ns = (kt + 2) % 3;
            int ko = (kt + 2) * 32;
            #pragma unroll
            for (int i = 0; i < 2; ++i) {
                cpa16(&As[ns][lm[i]][lq[i]>>1],
                      Ah + (size_t)(m0+lm[i])*512 + ko + lq[i], (m0+lm[i]) < M);
                cpa16(&Bs[ns][lm[i]][lq[i]>>1],
                      Bz + (size_t)(n0+lm[i])*512 + ko + lq[i], true);
            }
        }
        asm volatile("cp.async.commit_group;\n");

        #pragma unroll
        for (int ks = 0; ks < 2; ++ks) {
            int kb = ks * 8;
            uint32_t af[4][4], bf[4][2];
            #pragma unroll
            for (int mt = 0; mt < 4; ++mt) {
                int mb = wm*64 + mt*16;
                af[mt][0] = As[sl][mb+g  ][kb+t  ];
                af[mt][1] = As[sl][mb+g+8][kb+t  ];
                af[mt][2] = As[sl][mb+g  ][kb+t+4];
                af[mt][3] = As[sl][mb+g+8][kb+t+4];
            }
            #pragma unroll
            for (int nt = 0; nt < 4; ++nt) {
                int nb = wn*32 + nt*8;
                bf[nt][0] = Bs[sl][nb+g][kb+t  ];
                bf[nt][1] = Bs[sl][nb+g][kb+t+4];
            }
            #pragma unroll
            for (int mt = 0; mt < 4; ++mt)
                #pragma unroll
                for (int nt = 0; nt < 4; ++nt) {
                    asm volatile(
                        "mma.sync.aligned.m16n8k16.row.col.f32.f16.f16.f32 "
                        "{%0,%1,%2,%3}, {%4,%5,%6,%7}, {%8,%9}, {%0,%1,%2,%3};"
                        : "+f"(acc[mt][nt][0]), "+f"(acc[mt][nt][1]),
                          "+f"(acc[mt][nt][2]), "+f"(acc[mt][nt][3])
                        : "r"(af[mt][0]), "r"(af[mt][1]), "r"(af[mt][2]), "r"(af[mt][3]),
                          "r"(bf[nt][0]), "r"(bf[nt][1]));
                }
        }
    }

    #pragma unroll
    for (int mt = 0; mt < 4; ++mt) {
        int r0 = m0 + wm*64 + mt*16 + g;
        #pragma unroll
        for (int nt = 0; nt < 4; ++nt) {
            int c = n0 + wn*32 + nt*8 + t*2;
            float bv0 = __ldg(&bias[c]), bv1 = __ldg(&bias[c+1]);
            if (r0 < M)
                *(__half2*)&Ch[(size_t)r0*1024 + c] =
                    __floats2half2_rn(acc[mt][nt][0] + bv0, acc[mt][nt][1] + bv1);
            if (r0 + 8 < M)
                *(__half2*)&Ch[(size_t)(r0+8)*1024 + c] =
                    __floats2half2_rn(acc[mt][nt][2] + bv0, acc[mt][nt][3] + bv1);
        }
    }
}

// ---------------- final-GEMM f16 tensor kernel, split-K partials ----------------
__global__ void __launch_bounds__(256) gemmfin_f16_kernel(int M)
{
    __shared__ uint32_t As[2][128][20];
    __shared__ uint32_t Bs[2][128][20];

    int zs = blockIdx.z;
    int kbase = zs * 320;
    float* P = g_fpart + (size_t)zs*BB*1024;

    int tid  = threadIdx.x;
    int lane = tid & 31, wid = tid >> 5;
    int wm = wid >> 2, wn = wid & 3;
    int m0 = blockIdx.x * 128, n0 = blockIdx.y * 128;
    int g = lane >> 2, t = lane & 3;

    int lm[2], lq[2];
    #pragma unroll
    for (int i = 0; i < 2; ++i) {
        int idx = tid + i*256;
        lm[i] = idx >> 2;
        lq[i] = (idx & 3) * 8;
    }

    float acc[4][4][4];
    #pragma unroll
    for (int a = 0; a < 4; ++a)
        #pragma unroll
        for (int b = 0; b < 4; ++b)
            #pragma unroll
            for (int c = 0; c < 4; ++c) acc[a][b][c] = 0.f;

    float4 pa[2], pb[2];
    const int T = 10;

    #pragma unroll
    for (int i = 0; i < 2; ++i) {
        pa[i] = (m0 + lm[i] < M)
              ? *(const float4*)(g_cch + (size_t)(m0+lm[i])*1280 + kbase + lq[i])
              : make_float4(0.f,0.f,0.f,0.f);
        pb[i] = *(const float4*)(g_wfinh + (size_t)(n0+lm[i])*1280 + kbase + lq[i]);
    }
    #pragma unroll
    for (int i = 0; i < 2; ++i) {
        *(float4*)&As[0][lm[i]][lq[i]>>1] = pa[i];
        *(float4*)&Bs[0][lm[i]][lq[i]>>1] = pb[i];
    }
    __syncthreads();

    for (int kt = 0; kt < T; ++kt) {
        int b = kt & 1;
        if (kt + 1 < T) {
            int ko = kbase + (kt+1) * 32;
            #pragma unroll
            for (int i = 0; i < 2; ++i) {
                pa[i] = (m0 + lm[i] < M)
                      ? *(const float4*)(g_cch + (size_t)(m0+lm[i])*1280 + ko + lq[i])
                      : make_float4(0.f,0.f,0.f,0.f);
                pb[i] = *(const float4*)(g_wfinh + (size_t)(n0+lm[i])*1280 + ko + lq[i]);
            }
        }

        #pragma unroll
        for (int ks = 0; ks < 2; ++ks) {
            int kb = ks * 8;
            uint32_t af[4][4], bf[4][2];
            #pragma unroll
            for (int mt = 0; mt < 4; ++mt) {
                int mb = wm*64 + mt*16;
                af[mt][0] = As[b][mb+g  ][kb+t  ];
                af[mt][1] = As[b][mb+g+8][kb+t  ];
                af[mt][2] = As[b][mb+g  ][kb+t+4];
                af[mt][3] = As[b][mb+g+8][kb+t+4];
            }
            #pragma unroll
            for (int nt = 0; nt < 4; ++nt) {
                int nb = wn*32 + nt*8;
                bf[nt][0] = Bs[b][nb+g][kb+t  ];
                bf[nt][1] = Bs[b][nb+g][kb+t+4];
            }
            #pragma unroll
            for (int mt = 0; mt < 4; ++mt)
                #pragma unroll
                for (int nt = 0; nt < 4; ++nt) {
                    asm volatile(
                        "mma.sync.aligned.m16n8k16.row.col.f32.f16.f16.f32 "
                        "{%0,%1,%2,%3}, {%4,%5,%6,%7}, {%8,%9}, {%0,%1,%2,%3};"
                        : "+f"(acc[mt][nt][0]), "+f"(acc[mt][nt][1]),
                          "+f"(acc[mt][nt][2]), "+f"(acc[mt][nt][3])
                        : "r"(af[mt][0]), "r"(af[mt][1]), "r"(af[mt][2]), "r"(af[mt][3]),
                          "r"(bf[nt][0]), "r"(bf[nt][1]));
                }
        }

        if (kt + 1 < T) {
            int nb_ = b ^ 1;
            #pragma unroll
            for (int i = 0; i < 2; ++i) {
                *(float4*)&As[nb_][lm[i]][lq[i]>>1] = pa[i];
                *(float4*)&Bs[nb_][lm[i]][lq[i]>>1] = pb[i];
            }
            __syncthreads();
        }
    }

    #pragma unroll
    for (int mt = 0; mt < 4; ++mt) {
        int r0 = m0 + wm*64 + mt*16 + g;
        #pragma unroll
        for (int nt = 0; nt < 4; ++nt) {
            int c = n0 + wn*32 + nt*8 + t*2;
            if (r0 < M)
                *(float2*)&P[(size_t)r0*1024 + c] = make_float2(acc[mt][nt][0], acc[mt][nt][1]);
            if (r0 + 8 < M)
                *(float2*)&P[(size_t)(r0+8)*1024 + c] = make_float2(acc[mt][nt][2], acc[mt][nt][3]);
        }
    }
}

// ---------------- fp32 64x64 GEMM: pooled skip + z@Wv2 + edge/bias -> cch fp16 ------
__global__ void __launch_bounds__(256) gemm_pool64(
    const float* __restrict__ Ws2, const float* __restrict__ Wv2,
    const float* __restrict__ bs2,
    const float* __restrict__ We2, const float* __restrict__ bv2)
{
    __shared__ float As[16][68];
    __shared__ float Bs[16][68];
    int tid = threadIdx.x;
    int tx = tid & 15, ty = tid >> 4;
    int m0 = blockIdx.x * 64;
    int n0 = blockIdx.y * 64;
    int h = n0 >> 8;
    int hOff = h * 512;
    float acc[4][4] = {};

    int arow = tid >> 2, ac4 = (tid & 3)*4;
    int brow = tid >> 4, bc4 = (tid & 15)*4;

    #pragma unroll 1
    for (int half_ = 0; half_ < 2; ++half_) {
        const float* Bm = half_ ? Wv2 : Ws2;
        for (int k0 = 0; k0 < 512; k0 += 16) {
            float4 av = make_float4(0.f,0.f,0.f,0.f);
            if (m0 + arow < BB) {
                av = half_
                   ? __ldg((const float4*)&g_z[(size_t)(m0+arow)*2048 + hOff + k0 + ac4])
                   : __ldg((const float4*)&g_ph1[(size_t)(m0+arow)*512 + k0 + ac4]);
            }
            As[ac4+0][arow] = av.x; As[ac4+1][arow] = av.y;
            As[ac4+2][arow] = av.z; As[ac4+3][arow] = av.w;
            float4 bv = __ldg((const float4*)&Bm[(size_t)(k0+brow)*1024 + n0 + bc4]);
            *(float4*)&Bs[brow][bc4] = bv;
            __syncthreads();
            #pragma unroll
            for (int kk = 0; kk < 16; ++kk) {
                float a[4], b[4];
                *(float4*)a = *(const float4*)&As[kk][ty*4];
                *(float4*)b = *(const float4*)&Bs[kk][tx*4];
                #pragma unroll
                for (int i = 0; i < 4; ++i)
                    #pragma unroll
                    for (int j = 0; j < 4; ++j)
                        acc[i][j] = fmaf(a[i], b[j], acc[i][j]);
            }
            __syncthreads();
        }
    }
    #pragma unroll
    for (int i = 0; i < 4; ++i) {
        int row = m0 + ty*4 + i;
        if (row < BB) {
            float cfac = g_cnt[row] * (1.f/NPG);
            float r0 = g_r[row*16 + h*4 + 0], r1 = g_r[row*16 + h*4 + 1];
            float r2 = g_r[row*16 + h*4 + 2], r3 = g_r[row*16 + h*4 + 3];
            __half hbuf[4];
            #pragma unroll
            for (int j = 0; j < 4; ++j) {
                int col = n0 + tx*4 + j;
                float v = acc[i][j] + __ldg(&bs2[col]) + cfac*__ldg(&bv2[col]);
                v = fmaf(r0, __ldg(&We2[0*1024 + col]), v);
                v = fmaf(r1, __ldg(&We2[1*1024 + col]), v);
                v = fmaf(r2, __ldg(&We2[2*1024 + col]), v);
                v = fmaf(r3, __ldg(&We2[3*1024 + col]), v);
                hbuf[j] = __float2half_rn(v);
            }
            *(uint2*)&g_cch[(size_t)row*1280 + n0 + tx*4] = *(uint2*)hbuf;
        }
    }
}

// ---------------- fingerprint GEMM partials ----------------
__global__ void __launch_bounds__(256) gemm_fp64(
    const float* __restrict__ A, const float* __restrict__ Bm)
{
    __shared__ float As[16][68];
    __shared__ float Bs[16][68];
    int tid = threadIdx.x;
    int tx = tid & 15, ty = tid >> 4;
    int m0 = blockIdx.x * 64;
    int n0 = blockIdx.y * 64;
    int zs = blockIdx.z;
    int kb = zs * 512;
    float acc[4][4] = {};

    int arow = tid >> 2, ac4 = (tid & 3)*4;
    int brow = tid >> 4, bc4 = (tid & 15)*4;

    for (int k0 = kb; k0 < kb + 512; k0 += 16) {
        float4 av = make_float4(0.f,0.f,0.f,0.f);
        if (m0 + arow < BB)
            av = __ldg((const float4*)&A[(size_t)(m0+arow)*2048 + k0 + ac4]);
        As[ac4+0][arow] = av.x; As[ac4+1][arow] = av.y;
        As[ac4+2][arow] = av.z; As[ac4+3][arow] = av.w;
        float4 bv = __ldg((const float4*)&Bm[(size_t)(k0+brow)*256 + n0 + bc4]);
        *(float4*)&Bs[brow][bc4] = bv;
        __syncthreads();
        #pragma unroll
        for (int kk = 0; kk < 16; ++kk) {
            float a[4], b[4];
            *(float4*)a = *(const float4*)&As[kk][ty*4];
            *(float4*)b = *(const float4*)&Bs[kk][tx*4];
            #pragma unroll
            for (int i = 0; i < 4; ++i)
                #pragma unroll
                for (int j = 0; j < 4; ++j)
                    acc[i][j] = fmaf(a[i], b[j], acc[i][j]);
        }
        __syncthreads();
    }
    #pragma unroll
    for (int i = 0; i < 4; ++i) {
        int row = m0 + ty*4 + i;
        if (row < BB) {
            #pragma unroll
            for (int j = 0; j < 4; ++j) {
                int col = n0 + tx*4 + j;
                g_fppart[(size_t)zs*BB*256 + (size_t)row*256 + col] = acc[i][j];
            }
        }
    }
}

// ---------------- fingerprint cols -> cch fp16 ----------------
__global__ void fpcc_kernel(const float* __restrict__ bfp)
{
    int i = blockIdx.x*blockDim.x + threadIdx.x;
    if (i >= BB*128) return;
    int row = i >> 7;
    int cc = (i & 127) * 2;
    float v0 = __ldg(&bfp[cc]), v1 = __ldg(&bfp[cc+1]);
    #pragma unroll
    for (int zp = 0; zp < 4; ++zp) {
        v0 += g_fppart[(size_t)zp*BB*256 + (size_t)row*256 + cc];
        v1 += g_fppart[(size_t)zp*BB*256 + (size_t)row*256 + cc + 1];
    }
    *(__half2*)&g_cch[(size_t)row*1280 + 1024 + cc] = __floats2half2_rn(v0, v1);
}

// ---------------- final reduce ----------------
__global__ void reduce_fin_kernel(const float* __restrict__ bfin, float* __restrict__ out)
{
    int i = blockIdx.x*blockDim.x + threadIdx.x;
    if (i >= BB*256) return;
    int c4 = (i & 255) * 4;
    float4 acc = __ldg((const float4*)&bfin[c4]);
    #pragma unroll
    for (int zp = 0; zp < 4; ++zp) {
        float4 p = *(const float4*)&g_fpart[(size_t)zp*BB*1024 + (size_t)i*4];
        acc.x += p.x; acc.y += p.y; acc.z += p.z; acc.w += p.w;
    }
    ((float4*)out)[i] = acc;
}

// ---------------- launch (R13 schedule) ----------------
extern "C" void kernel_launch(void* const* d_in, const int* in_sizes, int n_in,
                              void* d_out, int out_size)
{
    const float* x    = (const float*)d_in[0];
    const int*   ei   = (const int*)  d_in[1];
    const float* ea   = (const float*)d_in[2];
    const float* fpb  = (const float*)d_in[4];
    const float *Wq1=(const float*)d_in[5],  *bq1=(const float*)d_in[6];
    const float *Wk1=(const float*)d_in[7],  *bk1=(const float*)d_in[8];
    const float *Wv1=(const float*)d_in[9],  *bv1=(const float*)d_in[10];
    const float *We1=(const float*)d_in[11];
    const float *Ws1=(const float*)d_in[12], *bs1=(const float*)d_in[13];
    const float *Wq2=(const float*)d_in[14], *bq2=(const float*)d_in[15];
    const float *Wk2=(const float*)d_in[16], *bk2=(const float*)d_in[17];
    const float *Wv2=(const float*)d_in[18], *bv2=(const float*)d_in[19];
    const float *We2=(const float*)d_in[20];
    const float *Ws2=(const float*)d_in[21], *bs2=(const float*)d_in[22];
    const float *Wfp=(const float*)d_in[23], *bfp=(const float*)d_in[24];
    const float *Wfin=(const float*)d_in[25],*bfin=(const float*)d_in[26];

    const int* srcArr = ei;
    const int* dstArr = ei + EE;

    float *ph1;
    __half *q1h,*s1h,*k1h,*v1h,*h1h,*q2h,*k2h;
    cudaGetSymbolAddress((void**)&q1h, g_q1h);
    cudaGetSymbolAddress((void**)&s1h, g_s1h);
    cudaGetSymbolAddress((void**)&k1h, g_k1h);
    cudaGetSymbolAddress((void**)&v1h, g_v1h);
    cudaGetSymbolAddress((void**)&h1h, g_h1h);
    cudaGetSymbolAddress((void**)&ph1, g_ph1);
    cudaGetSymbolAddress((void**)&q2h, g_q2h);
    cudaGetSymbolAddress((void**)&k2h, g_k2h);

    const int SM1 = 96*512;
    const int SM2 = 16*1024 + 2*NPG*1024 + NPG*1024
                  + 256*4*4*2 + 256*4 + NPG*4*4 + NPG*4 + 64;
    cudaFuncSetAttribute(attn1_kernel, cudaFuncAttributeMaxDynamicSharedMemorySize, SM1);
    cudaFuncSetAttribute(attn2_kernel, cudaFuncAttributeMaxDynamicSharedMemorySize, SM2);

    // ---- fork side stream ----
    cudaEventRecord(g_evA0, 0);
    cudaStreamWaitEvent(g_sB, g_evA0, 0);

    // side: CSR -> wt2half -> fp path
    zero_deg_kernel<<<(NN+255)/256, 256, 0, g_sB>>>();
    hist_kernel<<<(EE+255)/256, 256, 0, g_sB>>>(dstArr);
    scan_kernel<<<1, 1024, 0, g_sB>>>();
    scatter_kernel<<<(EE+255)/256, 256, 0, g_sB>>>(dstArr);
    sort_kernel<<<(NN+255)/256, 256, 0, g_sB>>>();
    cudaEventRecord(g_evCSR, g_sB);
    wt2half_kernel<<<dim3(32, 16, 2), dim3(32, 32), 0, g_sB>>>(Wq2, Wk2);
    cudaEventRecord(g_evB1, g_sB);
    wfin2half_kernel<<<dim3(32, 40), dim3(32, 32), 0, g_sB>>>(Wfin);
    gemm_fp64<<<dim3((BB+63)/64, 4, 4), 256, 0, g_sB>>>(fpb, Wfp);
    fpcc_kernel<<<(BB*128+255)/256, 256, 0, g_sB>>>(bfp);
    cudaEventRecord(g_evB2, g_sB);

    // main: layer 1
    proj1_kernel<<<(NN*32+255)/256, 256>>>(x, Wq1,bq1, Wk1,bk1, Wv1,bv1, Ws1,bs1);
    cudaStreamWaitEvent(0, g_evCSR, 0);
    attn1_kernel<<<BB, 640, SM1>>>(q1h, k1h, v1h, s1h, ea, We1, srcArr, ph1, h1h);

    // layer-2 q,k projections (needs wt2half)
    cudaStreamWaitEvent(0, g_evB1, 0);
    {
        dim3 grid((NN+127)/128, 1024/128, 2);
        gemm2_f16_kernel<<<grid, 256>>>(h1h, bq2, bk2, NN);
    }

    // layer-2 attention weights -> z, r, cnt
    attn2_kernel<<<BB, 640, SM2>>>(q2h, k2h, h1h, ea, We2, srcArr);

    // cch[:, :1024] = ph1@Ws2 + z@Wv2 + bs2 + edge/bias terms (fp16 direct)
    gemm_pool64<<<dim3((BB+63)/64, 1024/64), 256>>>(Ws2, Wv2, bs2, We2, bv2);

    // final GEMM (needs wfinh + fpcc via evB2)
    cudaStreamWaitEvent(0, g_evB2, 0);
    gemmfin_f16_kernel<<<dim3((BB+127)/128, 1024/128, 4), 256>>>(BB);
    reduce_fin_kernel<<<(BB*256+255)/256, 256>>>(bfin, (float*)d_out);
}